// round 7
// baseline (speedup 1.0000x reference)
#include <cuda_runtime.h>

#define NCTA 128
#define NTHR 512
#define TSTEPS 512
#define Bb 64
#define Hh 1024
#define K2H 2048
#define CHUNK 64

typedef unsigned long long u64_t;

// Persistent device state. All transposed: [col][row], row=batch.
__device__ float g_sT[9][Hh * Bb];
__device__ float g_hT[Hh * Bb];
__device__ float g_embT[Hh * Bb];
__device__ unsigned g_count = 0;   // monotonic across barriers AND graph replays
__device__ unsigned g_gen = 0;

// Staging buffer (x chunks) and reduction buffer are time-disjoint -> union (32KB).
union SmemU {
    float x[2][CHUNK * Bb];        // 2 x 16 KB double buffer
    u64_t red[8 * 32 * 16];        // 32 KB two-stage reduction
};

union F4U { float4 f; u64_t u[2]; };

// ---- packed f32x2 (Blackwell) ----
__device__ __forceinline__ u64_t pack2(float lo, float hi) {
    u64_t r; asm("mov.b64 %0, {%1, %2};" : "=l"(r) : "f"(lo), "f"(hi)); return r;
}
__device__ __forceinline__ void fma2(u64_t& d, u64_t a, u64_t b) {
    asm("fma.rn.f32x2 %0, %1, %2, %3;" : "=l"(d) : "l"(a), "l"(b), "l"(d));
}
__device__ __forceinline__ u64_t add2(u64_t a, u64_t b) {
    u64_t d; asm("add.rn.f32x2 %0, %1, %2;" : "=l"(d) : "l"(a), "l"(b)); return d;
}
__device__ __forceinline__ float ldcg_f(const float* p) {
    float v; asm volatile("ld.global.cg.f32 %0, [%1];" : "=f"(v) : "l"(p)); return v;
}
__device__ __forceinline__ void cp_async16(const float* smem_dst, const float* gsrc) {
    unsigned s = (unsigned)__cvta_generic_to_shared(smem_dst);
    asm volatile("cp.async.cg.shared.global [%0], [%1], 16;" :: "r"(s), "l"(gsrc));
}
#define CP_COMMIT() asm volatile("cp.async.commit_group;")
#define CP_WAIT1()  asm volatile("cp.async.wait_group 1;")
#define CP_WAIT0()  asm volatile("cp.async.wait_group 0;")

__device__ __forceinline__ float sigm(float x) { return 1.f / (1.f + expf(-x)); }
__device__ __forceinline__ float actf(int code, float x) {
    switch (code) {
        case 0:  return tanhf(x);
        case 1:  return fmaxf(x, 0.f);
        case 2:  return sigm(x);
        default: return x;
    }
}

// Monotonic-generation grid barrier (proven in R2-R4).
__device__ __forceinline__ void grid_sync() {
    __syncthreads();
    if (threadIdx.x == 0) {
        __threadfence();
        unsigned arr = atomicAdd(&g_count, 1u) + 1u;
        unsigned want = (arr + NCTA - 1u) / NCTA;
        if (arr % NCTA == 0u) atomicAdd(&g_gen, 1u);
        while (*((volatile unsigned*)&g_gen) < want) { }
        __threadfence();
    }
    __syncthreads();
}

// Cooperative stage of one x chunk (CHUNK k x 64 rows = 16KB) into smem via cp.async.cg.
__device__ __forceinline__ void stage_chunk(float* dst, const float* src) {
    const int t4 = threadIdx.x * 4;
    cp_async16(dst + t4,        src + t4);
    cp_async16(dst + t4 + 2048, src + t4 + 2048);
}

// One 8-col x 64-row output tile: out = gated(Sin); pre-act = x @ W (W:[K][2048], c|h halves).
// x transposed [k][64], staged through smem; 16 warps split each chunk's K.
__device__ __noinline__ void gemm_tile(
    const float* __restrict__ W, const float* __restrict__ xA,
    const float* __restrict__ xB, int Ka, int K,
    const float* __restrict__ gateT, float* __restrict__ outT,
    int j0, int act, SmemU* sm)
{
    const int lane = threadIdx.x & 31;
    const int warp = threadIdx.x >> 5;
    const int ct = lane & 1;           // 2 col-threads: 4 cols each
    const int g  = lane >> 1;          // 16 row-groups: 4 rows each
    const int colbase = j0 + ct * 4;
    const int rowbase = g * 4;
    const int NCH = K / CHUNK;

    u64_t acc[4][2][2];                // [row r][colpair cp][half h]
    #pragma unroll
    for (int r = 0; r < 4; r++)
        #pragma unroll
        for (int cp = 0; cp < 2; cp++) { acc[r][cp][0] = 0ull; acc[r][cp][1] = 0ull; }

    // prologue: stage chunk 0
    stage_chunk(sm->x[0], xA);
    CP_COMMIT();

    for (int c = 0; c < NCH; c++) {
        if (c + 1 < NCH) {
            int kb = (c + 1) * CHUNK;
            const float* src = (kb < Ka) ? (xA + (size_t)kb * Bb)
                                         : (xB + (size_t)(kb - Ka) * Bb);
            stage_chunk(sm->x[(c + 1) & 1], src);
            CP_COMMIT();
            CP_WAIT1();
        } else {
            CP_WAIT0();
        }
        __syncthreads();   // chunk c visible to all; prev buf fully consumed

        const float* xs = sm->x[c & 1] + (warp * 4) * Bb + rowbase;
        const float* wp = W + (size_t)(c * CHUNK + warp * 4) * K2H + colbase;

        #pragma unroll
        for (int kk = 0; kk < 4; kk++) {
            float4 xv = *(const float4*)(xs + kk * Bb);
            F4U wc, wh;
            wc.f = *(const float4*)(wp + (size_t)kk * K2H);
            wh.f = *(const float4*)(wp + (size_t)kk * K2H + Hh);
            u64_t xb;
            xb = pack2(xv.x, xv.x);
            fma2(acc[0][0][0], xb, wc.u[0]); fma2(acc[0][1][0], xb, wc.u[1]);
            fma2(acc[0][0][1], xb, wh.u[0]); fma2(acc[0][1][1], xb, wh.u[1]);
            xb = pack2(xv.y, xv.y);
            fma2(acc[1][0][0], xb, wc.u[0]); fma2(acc[1][1][0], xb, wc.u[1]);
            fma2(acc[1][0][1], xb, wh.u[0]); fma2(acc[1][1][1], xb, wh.u[1]);
            xb = pack2(xv.z, xv.z);
            fma2(acc[2][0][0], xb, wc.u[0]); fma2(acc[2][1][0], xb, wc.u[1]);
            fma2(acc[2][0][1], xb, wh.u[0]); fma2(acc[2][1][1], xb, wh.u[1]);
            xb = pack2(xv.w, xv.w);
            fma2(acc[3][0][0], xb, wc.u[0]); fma2(acc[3][1][0], xb, wc.u[1]);
            fma2(acc[3][0][1], xb, wh.u[0]); fma2(acc[3][1][1], xb, wh.u[1]);
        }
        __syncthreads();   // all reads of this buf done before it is restaged
    }

    // ---- reduction (reuses the same smem as red buffer) ----
    // Stage 1: warps 8..15 store partials into slot (warp-8).
    if (warp >= 8) {
        u64_t* my = sm->red + ((size_t)((warp - 8) * 32 + lane)) * 16;
        #pragma unroll
        for (int r = 0; r < 4; r++)
            #pragma unroll
            for (int cp = 0; cp < 2; cp++) {
                my[(r * 4 + cp * 2) + 0] = acc[r][cp][0];
                my[(r * 4 + cp * 2) + 1] = acc[r][cp][1];
            }
    }
    __syncthreads();

    // Stage 2: warps 0..7 add partner partials into slot warp.
    if (warp < 8) {
        u64_t* my = sm->red + ((size_t)(warp * 32 + lane)) * 16;
        #pragma unroll
        for (int r = 0; r < 4; r++)
            #pragma unroll
            for (int cp = 0; cp < 2; cp++) {
                int i0 = r * 4 + cp * 2;
                my[i0 + 0] = add2(my[i0 + 0], acc[r][cp][0]);
                my[i0 + 1] = add2(my[i0 + 1], acc[r][cp][1]);
            }
    }
    __syncthreads();

    // Stage 3: 512 threads finalize 512 outputs (8 cols x 64 rows).
    {
        const int t   = threadIdx.x;
        const int c8  = t & 7;
        const int row = t >> 3;
        const int sct = c8 >> 2;
        const int cp  = (c8 >> 1) & 1;
        const int par = c8 & 1;
        const int sg  = row >> 2;
        const int r   = row & 3;
        const int slane = sg * 2 + sct;
        const float* redf = (const float*)sm->red;
        const int fbase = slane * 32 + (r * 4 + cp * 2) * 2 + par;

        float sc = 0.f, sh = 0.f;
        #pragma unroll
        for (int s = 0; s < 8; s++) {
            const float* rp = redf + (size_t)s * 32 * 32 + fbase;
            sc += rp[0];
            sh += rp[2];
        }
        const int col = j0 + c8;
        const size_t o = (size_t)col * Bb + row;
        float sp = ldcg_f(gateT + o);
        float cv = sigm(sc);
        float hv = actf(act, sh);
        outT[o] = sp + cv * (hv - sp);
    }
    __syncthreads();
}

__global__ __launch_bounds__(NTHR, 1) void darts_persistent_kernel(
    const int* __restrict__ X, const float* __restrict__ hidden,
    const float* __restrict__ emb, const float* __restrict__ W0,
    const float* __restrict__ Ws, const float* __restrict__ Wout,
    const float* __restrict__ bout, float* __restrict__ out, int out_size)
{
    __shared__ SmemU sm;               // 32 KB (x staging) U (reduction)
    const int cta = blockIdx.x;
    const int tid = threadIdx.x;

    // init: transposed hidden and embT for t=0
    {
        int idx = cta * 512 + tid;
        int k = idx >> 6, row = idx & 63;
        g_hT[idx] = hidden[(size_t)row * Hh + k];
        int tok = __ldg(&X[row]);
        g_embT[idx] = __ldg(&emb[(size_t)tok * Hh + k]);
    }
    grid_sync();

    const size_t WSZ = (size_t)Hh * K2H;
    const int j0 = cta * 8;

    for (int t = 0; t < TSTEPS; t++) {
        // L0: s0 from [emb ; h] @ W0, gate base = h, act tanh
        gemm_tile(W0, g_embT, g_hT, Hh, K2H, g_hT, g_sT[0], j0, 0, &sm);
        grid_sync();

        // L1: s1 = node0(s0), sigmoid
        gemm_tile(Ws + 0 * WSZ, g_sT[0], g_sT[0], Hh, Hh, g_sT[0], g_sT[1], j0, 2, &sm);
        grid_sync();

        // L2: s2 = node1(s1) relu, s3 = node2(s1) relu, s4 = node3(s1) identity
        gemm_tile(Ws + 1 * WSZ, g_sT[1], g_sT[1], Hh, Hh, g_sT[1], g_sT[2], j0, 1, &sm);
        gemm_tile(Ws + 2 * WSZ, g_sT[1], g_sT[1], Hh, Hh, g_sT[1], g_sT[3], j0, 1, &sm);
        gemm_tile(Ws + 3 * WSZ, g_sT[1], g_sT[1], Hh, Hh, g_sT[1], g_sT[4], j0, 3, &sm);
        grid_sync();

        // L3: s5 = node4(s2), tanh
        gemm_tile(Ws + 4 * WSZ, g_sT[2], g_sT[2], Hh, Hh, g_sT[2], g_sT[5], j0, 0, &sm);
        grid_sync();

        // L4: s7 = node6(s3) tanh, s6 = node5(s5) sigmoid, s8 = node7(s5) relu
        gemm_tile(Ws + 6 * WSZ, g_sT[3], g_sT[3], Hh, Hh, g_sT[3], g_sT[7], j0, 0, &sm);
        gemm_tile(Ws + 5 * WSZ, g_sT[5], g_sT[5], Hh, Hh, g_sT[5], g_sT[6], j0, 2, &sm);
        gemm_tile(Ws + 7 * WSZ, g_sT[5], g_sT[5], Hh, Hh, g_sT[5], g_sT[8], j0, 1, &sm);

        // fused combine (own cols) + embT gather for t+1
        {
            int idx = cta * 512 + tid;
            float s = 0.f;
            #pragma unroll
            for (int n = 1; n <= 8; n++) s += ldcg_f(&g_sT[n][idx]);
            g_hT[idx] = s * 0.125f;
            if (t + 1 < TSTEPS) {
                int k = idx >> 6, row = idx & 63;
                int tok = __ldg(&X[(t + 1) * Bb + row]);
                g_embT[idx] = __ldg(&emb[(size_t)tok * Hh + k]);
            }
        }
        grid_sync();
    }

    // head: a_hat = h @ W_out + b_out; probs = softmax (4-wide, lane-aligned groups)
    if (cta == 0 && tid < 256) {
        int b = tid >> 2, o = tid & 3;
        float acc = 0.f;
        for (int k = 0; k < Hh; k++) acc += ldcg_f(&g_hT[(size_t)k * Bb + b]) * Wout[k * 4 + o];
        acc += bout[o];
        float m = acc;
        m = fmaxf(m, __shfl_xor_sync(0xFFFFFFFFu, m, 1));
        m = fmaxf(m, __shfl_xor_sync(0xFFFFFFFFu, m, 2));
        float e = expf(acc - m);
        float ssum = e;
        ssum += __shfl_xor_sync(0xFFFFFFFFu, ssum, 1);
        ssum += __shfl_xor_sync(0xFFFFFFFFu, ssum, 2);
        out[b * 4 + o] = acc;
        if (out_size >= 512) out[256 + b * 4 + o] = e / ssum;
    }
}

extern "C" void kernel_launch(void* const* d_in, const int* in_sizes, int n_in,
                              void* d_out, int out_size) {
    const int*   X      = (const int*)d_in[0];
    const float* hidden = (const float*)d_in[1];
    const float* emb    = (const float*)d_in[2];
    const float* W0     = (const float*)d_in[3];
    const float* Ws     = (const float*)d_in[4];
    const float* W_out  = (const float*)d_in[5];
    const float* b_out  = (const float*)d_in[6];
    (void)in_sizes; (void)n_in;

    darts_persistent_kernel<<<NCTA, NTHR>>>(X, hidden, emb, W0, Ws, W_out, b_out,
                                            (float*)d_out, out_size);
}